// round 5
// baseline (speedup 1.0000x reference)
#include <cuda_runtime.h>
#include <cuda_bf16.h>
#include <cstdint>
#include <math.h>

#define Nn 64
#define Cdim 128
#define Pdim 4096
#define Kdim 64
#define PSPLIT 4

// ---- device scratch ----
__device__ __nv_bfloat16 g_a[(size_t)Nn * Kdim * Pdim];      // 32 MB  (a * inv_norm, bf16)
__device__ float g_asum_p[Nn * 16 * Kdim];                    // 256 KB (per-tile asum partials)
__device__ float g_vpart[(size_t)Nn * PSPLIT * Cdim * Kdim];  // 8 MB   [n][ps][c][k]

// ---- mma / ldmatrix wrappers (baseline PTX, sm_80+, valid on sm_103) ----
__device__ __forceinline__ uint32_t smem_u32(const void* p) {
    uint32_t a;
    asm("{ .reg .u64 t; cvta.to.shared.u64 t, %1; cvt.u32.u64 %0, t; }" : "=r"(a) : "l"(p));
    return a;
}
__device__ __forceinline__ void ldsm_x4(uint32_t* r, uint32_t addr) {
    asm volatile("ldmatrix.sync.aligned.m8n8.x4.shared.b16 {%0,%1,%2,%3}, [%4];"
                 : "=r"(r[0]), "=r"(r[1]), "=r"(r[2]), "=r"(r[3]) : "r"(addr));
}
__device__ __forceinline__ void ldsm_x2_trans(uint32_t* r, uint32_t addr) {
    asm volatile("ldmatrix.sync.aligned.m8n8.x2.trans.shared.b16 {%0,%1}, [%2];"
                 : "=r"(r[0]), "=r"(r[1]) : "r"(addr));
}
__device__ __forceinline__ void mma_bf16(float* d, const uint32_t* a, const uint32_t* b) {
    asm volatile(
        "mma.sync.aligned.m16n8k16.row.col.f32.bf16.bf16.f32 "
        "{%0,%1,%2,%3}, {%4,%5,%6,%7}, {%8,%9}, {%0,%1,%2,%3};"
        : "+f"(d[0]), "+f"(d[1]), "+f"(d[2]), "+f"(d[3])
        : "r"(a[0]), "r"(a[1]), "r"(a[2]), "r"(a[3]), "r"(b[0]), "r"(b[1]));
}
__device__ __forceinline__ void split_bf16(float v, __nv_bfloat16& h, __nv_bfloat16& l) {
    h = __float2bfloat16(v);
    l = __float2bfloat16(v - __bfloat162float(h));
}

// =====================================================================
// K_logits_mma: per (n, 256-pixel tile). Register-prefetch pipeline.
// =====================================================================
#define L_WN 8704    // 64*136 elems per W plane
#define L_XN 8448    // 32*264 elems per x plane
#define L_SMEM 70144

__global__ __launch_bounds__(256, 2) void k_logits_mma(const float* __restrict__ x,
                                                       const float* __restrict__ conv_w,
                                                       const float* __restrict__ conv_b) {
    extern __shared__ __align__(16) char dsm[];
    __nv_bfloat16* wh = (__nv_bfloat16*)dsm;
    __nv_bfloat16* wl = wh + L_WN;
    __nv_bfloat16* xh = wl + L_WN;
    __nv_bfloat16* xl = xh + L_XN;
    __nv_bfloat16* aout = xh;                  // alias: 64*264 == 2*32*264
    float* s_sumsq = (float*)(xl + L_XN);      // 256
    float* s_asum = s_sumsq + 256;             // 64
    float* s_b = s_asum + 64;                  // 64

    const int n = blockIdx.y;
    const int p0 = blockIdx.x * 256;
    const int tid = threadIdx.x;
    const int w = tid >> 5, lane = tid & 31;
    const int pw = w * 32;

    const uint32_t u_wh = smem_u32(wh), u_wl = smem_u32(wl);
    const uint32_t u_xh = smem_u32(xh), u_xl = smem_u32(xl);

#pragma unroll
    for (int r = 0; r < 8; ++r) {
        int f4 = tid + r * 256;
        int row = f4 >> 5, col4 = f4 & 31;
        float4 v = *(const float4*)(conv_w + row * 128 + col4 * 4);
        __nv_bfloat16 h, l;
        split_bf16(v.x, h, l); wh[row * 136 + col4 * 4 + 0] = h; wl[row * 136 + col4 * 4 + 0] = l;
        split_bf16(v.y, h, l); wh[row * 136 + col4 * 4 + 1] = h; wl[row * 136 + col4 * 4 + 1] = l;
        split_bf16(v.z, h, l); wh[row * 136 + col4 * 4 + 2] = h; wl[row * 136 + col4 * 4 + 2] = l;
        split_bf16(v.w, h, l); wh[row * 136 + col4 * 4 + 3] = h; wl[row * 136 + col4 * 4 + 3] = l;
    }
    if (tid < 64) { s_b[tid] = conv_b[tid]; s_asum[tid] = 0.f; }
    s_sumsq[tid] = 0.f;

    float acc[4][4][4];
#pragma unroll
    for (int a = 0; a < 4; ++a)
#pragma unroll
        for (int b = 0; b < 4; ++b)
#pragma unroll
            for (int c = 0; c < 4; ++c) acc[a][b][c] = 0.f;

    const float* xg = x + (size_t)n * Cdim * Pdim + p0;
    // staging geometry: this thread owns pixel-quad col4 (fixed), rows rbase+4r
    const int rbase = tid >> 6;          // 0..3
    const int col4 = tid & 63;           // pixel quad

    float4 vx[8];
#pragma unroll
    for (int r = 0; r < 8; ++r)
        vx[r] = *(const float4*)(xg + (size_t)(rbase + 4 * r) * Pdim + col4 * 4);

    for (int cbi = 0; cbi < 4; ++cbi) {
        const int cb = cbi * 32;
        // convert+store staged regs -> smem planes; accumulate sumsq from regs
        float ssx = 0.f, ssy = 0.f, ssz = 0.f, ssw = 0.f;
#pragma unroll
        for (int r = 0; r < 8; ++r) {
            int row = rbase + 4 * r;
            float4 v = vx[r];
            ssx += v.x * v.x; ssy += v.y * v.y; ssz += v.z * v.z; ssw += v.w * v.w;
            __nv_bfloat16 h, l;
            split_bf16(v.x, h, l); xh[row * 264 + col4 * 4 + 0] = h; xl[row * 264 + col4 * 4 + 0] = l;
            split_bf16(v.y, h, l); xh[row * 264 + col4 * 4 + 1] = h; xl[row * 264 + col4 * 4 + 1] = l;
            split_bf16(v.z, h, l); xh[row * 264 + col4 * 4 + 2] = h; xl[row * 264 + col4 * 4 + 2] = l;
            split_bf16(v.w, h, l); xh[row * 264 + col4 * 4 + 3] = h; xl[row * 264 + col4 * 4 + 3] = l;
        }
        atomicAdd(&s_sumsq[col4 * 4 + 0], ssx);
        atomicAdd(&s_sumsq[col4 * 4 + 1], ssy);
        atomicAdd(&s_sumsq[col4 * 4 + 2], ssz);
        atomicAdd(&s_sumsq[col4 * 4 + 3], ssw);
        __syncthreads();

        // prefetch next chunk (overlaps with MMAs below)
        if (cbi < 3) {
#pragma unroll
            for (int r = 0; r < 8; ++r)
                vx[r] = *(const float4*)(xg + (size_t)(cb + 32 + rbase + 4 * r) * Pdim + col4 * 4);
        }

#pragma unroll
        for (int ks = 0; ks < 2; ++ks) {
            uint32_t bh[4][2], bl[4][2];
#pragma unroll
            for (int nt = 0; nt < 4; ++nt) {
                uint32_t off = (uint32_t)(((ks * 16 + (lane & 15)) * 264 + pw + nt * 8) * 2);
                ldsm_x2_trans(bh[nt], u_xh + off);
                ldsm_x2_trans(bl[nt], u_xl + off);
            }
#pragma unroll
            for (int mt = 0; mt < 4; ++mt) {
                uint32_t ah[4], al[4];
                uint32_t off = (uint32_t)(((mt * 16 + (lane & 15)) * 136 + cb + ks * 16 + (lane >> 4) * 8) * 2);
                ldsm_x4(ah, u_wh + off);
                ldsm_x4(al, u_wl + off);
#pragma unroll
                for (int nt = 0; nt < 4; ++nt) {
                    mma_bf16(acc[mt][nt], ah, bh[nt]);
                    mma_bf16(acc[mt][nt], ah, bl[nt]);
                    mma_bf16(acc[mt][nt], al, bh[nt]);
                }
            }
        }
        __syncthreads();
    }
    s_sumsq[tid] = 1.f / fmaxf(sqrtf(s_sumsq[tid]), 1e-12f);
    __syncthreads();
    float* s_inv = s_sumsq;

    float iv0[4], iv1[4];
#pragma unroll
    for (int nt = 0; nt < 4; ++nt) {
        int c0 = pw + nt * 8 + (lane & 3) * 2;
        iv0[nt] = s_inv[c0];
        iv1[nt] = s_inv[c0 + 1];
    }
    float bb0[4], bb1[4];
#pragma unroll
    for (int mt = 0; mt < 4; ++mt) {
        bb0[mt] = s_b[mt * 16 + (lane >> 2)];
        bb1[mt] = s_b[mt * 16 + (lane >> 2) + 8];
    }
    float l[4][4][4];
#pragma unroll
    for (int mt = 0; mt < 4; ++mt)
#pragma unroll
        for (int nt = 0; nt < 4; ++nt) {
            l[mt][nt][0] = acc[mt][nt][0] * iv0[nt] + bb0[mt];
            l[mt][nt][1] = acc[mt][nt][1] * iv1[nt] + bb0[mt];
            l[mt][nt][2] = acc[mt][nt][2] * iv0[nt] + bb1[mt];
            l[mt][nt][3] = acc[mt][nt][3] * iv1[nt] + bb1[mt];
        }
    float mx0[4], mx1[4];
#pragma unroll
    for (int nt = 0; nt < 4; ++nt) {
        float m0 = -1e30f, m1 = -1e30f;
#pragma unroll
        for (int mt = 0; mt < 4; ++mt) {
            m0 = fmaxf(m0, fmaxf(l[mt][nt][0], l[mt][nt][2]));
            m1 = fmaxf(m1, fmaxf(l[mt][nt][1], l[mt][nt][3]));
        }
#pragma unroll
        for (int s = 4; s < 32; s <<= 1) {
            m0 = fmaxf(m0, __shfl_xor_sync(0xffffffffu, m0, s));
            m1 = fmaxf(m1, __shfl_xor_sync(0xffffffffu, m1, s));
        }
        mx0[nt] = m0; mx1[nt] = m1;
    }
    float sm0[4], sm1[4];
#pragma unroll
    for (int nt = 0; nt < 4; ++nt) {
        float s0 = 0.f, s1 = 0.f;
#pragma unroll
        for (int mt = 0; mt < 4; ++mt) {
            l[mt][nt][0] = __expf(l[mt][nt][0] - mx0[nt]); s0 += l[mt][nt][0];
            l[mt][nt][2] = __expf(l[mt][nt][2] - mx0[nt]); s0 += l[mt][nt][2];
            l[mt][nt][1] = __expf(l[mt][nt][1] - mx1[nt]); s1 += l[mt][nt][1];
            l[mt][nt][3] = __expf(l[mt][nt][3] - mx1[nt]); s1 += l[mt][nt][3];
        }
#pragma unroll
        for (int s = 4; s < 32; s <<= 1) {
            s0 += __shfl_xor_sync(0xffffffffu, s0, s);
            s1 += __shfl_xor_sync(0xffffffffu, s1, s);
        }
        sm0[nt] = 1.f / s0; sm1[nt] = 1.f / s1;
    }
    float srow0[4] = {0, 0, 0, 0}, srow1[4] = {0, 0, 0, 0};
#pragma unroll
    for (int mt = 0; mt < 4; ++mt) {
        int r0 = mt * 16 + (lane >> 2);
#pragma unroll
        for (int nt = 0; nt < 4; ++nt) {
            int c0 = pw + nt * 8 + (lane & 3) * 2;
            float a0 = l[mt][nt][0] * sm0[nt];
            float a1 = l[mt][nt][1] * sm1[nt];
            float a2 = l[mt][nt][2] * sm0[nt];
            float a3 = l[mt][nt][3] * sm1[nt];
            srow0[mt] += a0 + a1;
            srow1[mt] += a2 + a3;
            __nv_bfloat162 t0(__float2bfloat16(a0 * iv0[nt]), __float2bfloat16(a1 * iv1[nt]));
            __nv_bfloat162 t1(__float2bfloat16(a2 * iv0[nt]), __float2bfloat16(a3 * iv1[nt]));
            *(__nv_bfloat162*)&aout[r0 * 264 + c0] = t0;
            *(__nv_bfloat162*)&aout[(r0 + 8) * 264 + c0] = t1;
        }
    }
#pragma unroll
    for (int mt = 0; mt < 4; ++mt) {
        float t0 = srow0[mt], t1 = srow1[mt];
        t0 += __shfl_xor_sync(0xffffffffu, t0, 1); t0 += __shfl_xor_sync(0xffffffffu, t0, 2);
        t1 += __shfl_xor_sync(0xffffffffu, t1, 1); t1 += __shfl_xor_sync(0xffffffffu, t1, 2);
        if ((lane & 3) == 0) {
            atomicAdd(&s_asum[mt * 16 + (lane >> 2)], t0);
            atomicAdd(&s_asum[mt * 16 + (lane >> 2) + 8], t1);
        }
    }
    __syncthreads();
    __nv_bfloat16* ga = g_a + (size_t)(n * Kdim) * Pdim + p0;
#pragma unroll
    for (int r = 0; r < 8; ++r) {
        int f = tid + r * 256;
        int row = f >> 5, seg = f & 31;
        *(uint4*)(ga + (size_t)row * Pdim + seg * 8) = *(uint4*)&aout[row * 264 + seg * 8];
    }
    if (tid < 64) g_asum_p[(n * 16 + blockIdx.x) * Kdim + tid] = s_asum[tid];
}

// =====================================================================
// K_vlad_mma: single-term bf16 x (raw), bf16 a'. Register-prefetch pipeline.
// =====================================================================
__global__ __launch_bounds__(256, 2) void k_vlad_mma(const float* __restrict__ x) {
    __shared__ __align__(16) __nv_bfloat16 xh[128 * 72];
    __shared__ __align__(16) __nv_bfloat16 as_[64 * 72];

    const int n = blockIdx.y, ps = blockIdx.x;
    const int tid = threadIdx.x;
    const int w = tid >> 5, lane = tid & 31;
    const int pb0 = ps * (Pdim / PSPLIT);

    const uint32_t u_xh = smem_u32(xh), u_as = smem_u32(as_);

    float acc[8][4];
#pragma unroll
    for (int a = 0; a < 8; ++a)
#pragma unroll
        for (int b = 0; b < 4; ++b) acc[a][b] = 0.f;

    const float* xg = x + (size_t)n * Cdim * Pdim;
    const __nv_bfloat16* ga = g_a + (size_t)(n * Kdim) * Pdim;

    const int xrow = tid >> 4, xcol4 = tid & 15;
    const int arow = tid >> 3, aseg = tid & 7;

    float4 vx[8];
    uint4 va[2];
#pragma unroll
    for (int r = 0; r < 8; ++r)
        vx[r] = *(const float4*)(xg + (size_t)(xrow + r * 16) * Pdim + pb0 + xcol4 * 4);
#pragma unroll
    for (int r = 0; r < 2; ++r)
        va[r] = *(const uint4*)(ga + (size_t)(arow + r * 32) * Pdim + pb0 + aseg * 8);

    for (int pc = 0; pc < 16; ++pc) {
#pragma unroll
        for (int r = 0; r < 8; ++r) {
            __nv_bfloat162 h01(__float2bfloat16(vx[r].x), __float2bfloat16(vx[r].y));
            __nv_bfloat162 h23(__float2bfloat16(vx[r].z), __float2bfloat16(vx[r].w));
            *(__nv_bfloat162*)&xh[(xrow + r * 16) * 72 + xcol4 * 4] = h01;
            *(__nv_bfloat162*)&xh[(xrow + r * 16) * 72 + xcol4 * 4 + 2] = h23;
        }
#pragma unroll
        for (int r = 0; r < 2; ++r)
            *(uint4*)&as_[(arow + r * 32) * 72 + aseg * 8] = va[r];
        __syncthreads();

        if (pc < 15) {
            const int pb = pb0 + (pc + 1) * 64;
#pragma unroll
            for (int r = 0; r < 8; ++r)
                vx[r] = *(const float4*)(xg + (size_t)(xrow + r * 16) * Pdim + pb + xcol4 * 4);
#pragma unroll
            for (int r = 0; r < 2; ++r)
                va[r] = *(const uint4*)(ga + (size_t)(arow + r * 32) * Pdim + pb + aseg * 8);
        }

#pragma unroll
        for (int ks = 0; ks < 4; ++ks) {
            uint32_t ah[4];
            uint32_t offA = (uint32_t)(((w * 16 + (lane & 15)) * 72 + ks * 16 + (lane >> 4) * 8) * 2);
            ldsm_x4(ah, u_xh + offA);
#pragma unroll
            for (int ntp = 0; ntp < 4; ++ntp) {
                uint32_t b4[4];
                int row = ntp * 16 + ((lane >> 4) << 3) + (lane & 7);
                int col = ks * 16 + ((lane >> 3) & 1) * 8;
                ldsm_x4(b4, u_as + (uint32_t)((row * 72 + col) * 2));
                mma_bf16(acc[2 * ntp], ah, b4);
                mma_bf16(acc[2 * ntp + 1], ah, b4 + 2);
            }
        }
        __syncthreads();
    }
    float* vp = g_vpart + (size_t)(n * PSPLIT + ps) * (Cdim * Kdim);
    int r0 = w * 16 + (lane >> 2);
    int c0 = (lane & 3) * 2;
#pragma unroll
    for (int nt = 0; nt < 8; ++nt) {
        float2 t0 = make_float2(acc[nt][0], acc[nt][1]);
        float2 t1 = make_float2(acc[nt][2], acc[nt][3]);
        *(float2*)&vp[(size_t)r0 * Kdim + nt * 8 + c0] = t0;
        *(float2*)&vp[(size_t)(r0 + 8) * Kdim + nt * 8 + c0] = t1;
    }
}

// =====================================================================
// K_final: 1024 threads.
// =====================================================================
__global__ __launch_bounds__(1024) void k_final(const float* __restrict__ cent,
                                                float* __restrict__ out) {
    const int n = blockIdx.x;
    const int tid = threadIdx.x;
    __shared__ float vl[Kdim * 129];
    __shared__ float rn[Kdim];
    __shared__ float redb[32];
    __shared__ float s_asum[64];
    __shared__ float gscale;

    if (tid < 64) {
        float s = 0.f;
#pragma unroll
        for (int t = 0; t < 16; ++t) s += g_asum_p[(n * 16 + t) * Kdim + tid];
        s_asum[tid] = s;
    }
    __syncthreads();

    const float* vp = g_vpart + (size_t)(n * PSPLIT) * (Cdim * Kdim);
#pragma unroll
    for (int it = 0; it < 2; ++it) {
        int i4 = tid + it * 1024;
        int idx = i4 * 4;
        float4 s = *(const float4*)(vp + idx);
        float4 s1 = *(const float4*)(vp + (Cdim * Kdim) + idx);
        float4 s2 = *(const float4*)(vp + 2 * (Cdim * Kdim) + idx);
        float4 s3 = *(const float4*)(vp + 3 * (Cdim * Kdim) + idx);
        s.x += s1.x + s2.x + s3.x;
        s.y += s1.y + s2.y + s3.y;
        s.z += s1.z + s2.z + s3.z;
        s.w += s1.w + s2.w + s3.w;
        int c = idx >> 6, k = idx & 63;
        vl[(k + 0) * 129 + c] = s.x - s_asum[k + 0] * cent[(k + 0) * Cdim + c];
        vl[(k + 1) * 129 + c] = s.y - s_asum[k + 1] * cent[(k + 1) * Cdim + c];
        vl[(k + 2) * 129 + c] = s.z - s_asum[k + 2] * cent[(k + 2) * Cdim + c];
        vl[(k + 3) * 129 + c] = s.w - s_asum[k + 3] * cent[(k + 3) * Cdim + c];
    }
    __syncthreads();

    int w = tid >> 5, lane = tid & 31;
#pragma unroll
    for (int kk = 0; kk < 2; ++kk) {
        int k = w * 2 + kk;
        float t = 0.f;
#pragma unroll
        for (int m = 0; m < 4; ++m) {
            float v = vl[k * 129 + lane + m * 32];
            t += v * v;
        }
#pragma unroll
        for (int off = 16; off > 0; off >>= 1) t += __shfl_xor_sync(0xffffffffu, t, off);
        if (lane == 0) rn[k] = 1.f / fmaxf(sqrtf(t), 1e-12f);
    }
    __syncthreads();

    float tot = 0.f;
#pragma unroll
    for (int it = 0; it < 8; ++it) {
        int idx = tid + it * 1024;
        int k = idx >> 7, c = idx & 127;
        float v = vl[k * 129 + c] * rn[k];
        vl[k * 129 + c] = v;
        tot += v * v;
    }
#pragma unroll
    for (int off = 16; off > 0; off >>= 1) tot += __shfl_xor_sync(0xffffffffu, tot, off);
    if (lane == 0) redb[w] = tot;
    __syncthreads();
    if (tid == 0) {
        float t = 0.f;
#pragma unroll
        for (int q = 0; q < 32; ++q) t += redb[q];
        gscale = 1.f / fmaxf(sqrtf(t), 1e-12f);
    }
    __syncthreads();
    float gs = gscale;
#pragma unroll
    for (int it = 0; it < 8; ++it) {
        int idx = tid + it * 1024;
        int k = idx >> 7, c = idx & 127;
        out[(size_t)n * (Kdim * Cdim) + idx] = vl[k * 129 + c] * gs;
    }
}

// =====================================================================
extern "C" void kernel_launch(void* const* d_in, const int* in_sizes, int n_in,
                              void* d_out, int out_size) {
    const float* x      = (const float*)d_in[0];
    const float* cent   = (const float*)d_in[2];
    const float* conv_w = (const float*)d_in[3];
    const float* conv_b = (const float*)d_in[4];
    float* out = (float*)d_out;

    cudaFuncSetAttribute(k_logits_mma, cudaFuncAttributeMaxDynamicSharedMemorySize, L_SMEM);

    k_logits_mma<<<dim3(16, 64), 256, L_SMEM>>>(x, conv_w, conv_b);
    k_vlad_mma<<<dim3(PSPLIT, 64), 256>>>(x);
    k_final<<<64, 1024>>>(cent, out);
}

// round 6
// speedup vs baseline: 1.0442x; 1.0442x over previous
#include <cuda_runtime.h>
#include <cuda_bf16.h>
#include <cstdint>
#include <math.h>

#define Nn 64
#define Cdim 128
#define Pdim 4096
#define Kdim 64
#define PSPLIT 4

// ---- device scratch ----
__device__ __nv_bfloat16 g_a[(size_t)Nn * Kdim * Pdim];      // 32 MB  (a * inv_norm, bf16)
__device__ float g_asum_p[Nn * 16 * Kdim];                    // 256 KB (per-tile asum partials)
__device__ float g_vpart[(size_t)Nn * PSPLIT * Cdim * Kdim];  // 8 MB   [n][ps][c][k]

// ---- mma / ldmatrix wrappers (baseline PTX, sm_80+, valid on sm_103) ----
__device__ __forceinline__ uint32_t smem_u32(const void* p) {
    uint32_t a;
    asm("{ .reg .u64 t; cvta.to.shared.u64 t, %1; cvt.u32.u64 %0, t; }" : "=r"(a) : "l"(p));
    return a;
}
__device__ __forceinline__ void ldsm_x4(uint32_t* r, uint32_t addr) {
    asm volatile("ldmatrix.sync.aligned.m8n8.x4.shared.b16 {%0,%1,%2,%3}, [%4];"
                 : "=r"(r[0]), "=r"(r[1]), "=r"(r[2]), "=r"(r[3]) : "r"(addr));
}
__device__ __forceinline__ void ldsm_x2_trans(uint32_t* r, uint32_t addr) {
    asm volatile("ldmatrix.sync.aligned.m8n8.x2.trans.shared.b16 {%0,%1}, [%2];"
                 : "=r"(r[0]), "=r"(r[1]) : "r"(addr));
}
__device__ __forceinline__ void mma_bf16(float* d, const uint32_t* a, const uint32_t* b) {
    asm volatile(
        "mma.sync.aligned.m16n8k16.row.col.f32.bf16.bf16.f32 "
        "{%0,%1,%2,%3}, {%4,%5,%6,%7}, {%8,%9}, {%0,%1,%2,%3};"
        : "+f"(d[0]), "+f"(d[1]), "+f"(d[2]), "+f"(d[3])
        : "r"(a[0]), "r"(a[1]), "r"(a[2]), "r"(a[3]), "r"(b[0]), "r"(b[1]));
}
__device__ __forceinline__ void split_bf16(float v, __nv_bfloat16& h, __nv_bfloat16& l) {
    h = __float2bfloat16(v);
    l = __float2bfloat16(v - __bfloat162float(h));
}
// packed pair: element0 (low 16 bits) = lo arg, element1 = hi arg
__device__ __forceinline__ uint32_t cvt2bf(float lo, float hi) {
    uint32_t r;
    asm("cvt.rn.bf16x2.f32 %0, %1, %2;" : "=r"(r) : "f"(hi), "f"(lo));
    return r;
}
__device__ __forceinline__ float bfp_lo(uint32_t pair) { return __uint_as_float(pair << 16); }
__device__ __forceinline__ float bfp_hi(uint32_t pair) { return __uint_as_float(pair & 0xFFFF0000u); }

// =====================================================================
// K_logits_mma: per (n, 256-pixel tile). Double-buffered x planes,
// reg-accumulated sumsq, pair conversions.
// =====================================================================
#define L_XP 8448                  // 32*264 elems per x plane
#define OFF_WH 0
#define OFF_WL 17408
#define OFF_XB 34816               // 4 planes * 16896 B
#define OFF_SP 102400              // s_part 4*256 floats
#define OFF_SA 106496              // s_asum 64 floats
#define OFF_SB 106752              // s_b 64 floats
#define L_SMEM 107008

__global__ __launch_bounds__(256, 2) void k_logits_mma(const float* __restrict__ x,
                                                       const float* __restrict__ conv_w,
                                                       const float* __restrict__ conv_b) {
    extern __shared__ __align__(16) char dsm[];
    __nv_bfloat16* wh = (__nv_bfloat16*)(dsm + OFF_WH);
    __nv_bfloat16* wl = (__nv_bfloat16*)(dsm + OFF_WL);
    __nv_bfloat16* xb = (__nv_bfloat16*)(dsm + OFF_XB);
    __nv_bfloat16* aout = xb;                    // alias after mainloop
    float* s_part = (float*)(dsm + OFF_SP);
    float* s_asum = (float*)(dsm + OFF_SA);
    float* s_b = (float*)(dsm + OFF_SB);

    const int n = blockIdx.y;
    const int p0 = blockIdx.x * 256;
    const int tid = threadIdx.x;
    const int w = tid >> 5, lane = tid & 31;
    const int pw = w * 32;

    const uint32_t u_wh = smem_u32(wh), u_wl = smem_u32(wl);

#pragma unroll
    for (int r = 0; r < 8; ++r) {
        int f4 = tid + r * 256;
        int row = f4 >> 5, col4 = f4 & 31;
        float4 v = *(const float4*)(conv_w + row * 128 + col4 * 4);
        __nv_bfloat16 h, l;
        split_bf16(v.x, h, l); wh[row * 136 + col4 * 4 + 0] = h; wl[row * 136 + col4 * 4 + 0] = l;
        split_bf16(v.y, h, l); wh[row * 136 + col4 * 4 + 1] = h; wl[row * 136 + col4 * 4 + 1] = l;
        split_bf16(v.z, h, l); wh[row * 136 + col4 * 4 + 2] = h; wl[row * 136 + col4 * 4 + 2] = l;
        split_bf16(v.w, h, l); wh[row * 136 + col4 * 4 + 3] = h; wl[row * 136 + col4 * 4 + 3] = l;
    }
    if (tid < 64) { s_b[tid] = conv_b[tid]; s_asum[tid] = 0.f; }

    float acc[4][4][4];
#pragma unroll
    for (int a = 0; a < 4; ++a)
#pragma unroll
        for (int b = 0; b < 4; ++b)
#pragma unroll
            for (int c = 0; c < 4; ++c) acc[a][b][c] = 0.f;

    const float* xg = x + (size_t)n * Cdim * Pdim + p0;
    const int rbase = tid >> 6;          // 0..3
    const int col4 = tid & 63;           // pixel quad

    float ss0 = 0.f, ss1 = 0.f, ss2 = 0.f, ss3 = 0.f;
    float4 vx[8];

    // prologue: chunk 0 load + stage into buffer 0
#pragma unroll
    for (int r = 0; r < 8; ++r)
        vx[r] = *(const float4*)(xg + (size_t)(rbase + 4 * r) * Pdim + col4 * 4);
    {
        __nv_bfloat16* cxh = xb;
        __nv_bfloat16* cxl = xb + L_XP;
#pragma unroll
        for (int r = 0; r < 8; ++r) {
            float4 v = vx[r];
            ss0 += v.x * v.x; ss1 += v.y * v.y; ss2 += v.z * v.z; ss3 += v.w * v.w;
            uint32_t h01 = cvt2bf(v.x, v.y), h23 = cvt2bf(v.z, v.w);
            float l0 = v.x - bfp_lo(h01), l1 = v.y - bfp_hi(h01);
            float l2 = v.z - bfp_lo(h23), l3 = v.w - bfp_hi(h23);
            int row = rbase + 4 * r;
            *(uint2*)&cxh[row * 264 + col4 * 4] = make_uint2(h01, h23);
            *(uint2*)&cxl[row * 264 + col4 * 4] = make_uint2(cvt2bf(l0, l1), cvt2bf(l2, l3));
        }
    }
    __syncthreads();

#pragma unroll
    for (int cbi = 0; cbi < 4; ++cbi) {
        const int cb = cbi * 32;
        // global prefetch for next chunk (lands during MMA below)
        if (cbi < 3) {
#pragma unroll
            for (int r = 0; r < 8; ++r)
                vx[r] = *(const float4*)(xg + (size_t)(cb + 32 + rbase + 4 * r) * Pdim + col4 * 4);
        }

        const uint32_t u_xh = smem_u32(xb + (cbi & 1) * 2 * L_XP);
        const uint32_t u_xl = u_xh + L_XP * 2;
#pragma unroll
        for (int ks = 0; ks < 2; ++ks) {
            uint32_t bh[4][2], bl[4][2];
#pragma unroll
            for (int nt = 0; nt < 4; ++nt) {
                uint32_t off = (uint32_t)(((ks * 16 + (lane & 15)) * 264 + pw + nt * 8) * 2);
                ldsm_x2_trans(bh[nt], u_xh + off);
                ldsm_x2_trans(bl[nt], u_xl + off);
            }
#pragma unroll
            for (int mt = 0; mt < 4; ++mt) {
                uint32_t ah[4], al[4];
                uint32_t off = (uint32_t)(((mt * 16 + (lane & 15)) * 136 + cb + ks * 16 + (lane >> 4) * 8) * 2);
                ldsm_x4(ah, u_wh + off);
                ldsm_x4(al, u_wl + off);
#pragma unroll
                for (int nt = 0; nt < 4; ++nt) {
                    mma_bf16(acc[mt][nt], ah, bh[nt]);
                    mma_bf16(acc[mt][nt], ah, bl[nt]);
                    mma_bf16(acc[mt][nt], al, bh[nt]);
                }
            }
        }

        // stage next chunk into the other buffer (overlaps other warps' MMAs)
        if (cbi < 3) {
            __nv_bfloat16* cxh = xb + ((cbi + 1) & 1) * 2 * L_XP;
            __nv_bfloat16* cxl = cxh + L_XP;
#pragma unroll
            for (int r = 0; r < 8; ++r) {
                float4 v = vx[r];
                ss0 += v.x * v.x; ss1 += v.y * v.y; ss2 += v.z * v.z; ss3 += v.w * v.w;
                uint32_t h01 = cvt2bf(v.x, v.y), h23 = cvt2bf(v.z, v.w);
                float l0 = v.x - bfp_lo(h01), l1 = v.y - bfp_hi(h01);
                float l2 = v.z - bfp_lo(h23), l3 = v.w - bfp_hi(h23);
                int row = rbase + 4 * r;
                *(uint2*)&cxh[row * 264 + col4 * 4] = make_uint2(h01, h23);
                *(uint2*)&cxl[row * 264 + col4 * 4] = make_uint2(cvt2bf(l0, l1), cvt2bf(l2, l3));
            }
        }
        __syncthreads();
    }

    // sumsq reduce: s_part[rbase][pixel]
    *(float4*)&s_part[rbase * 256 + col4 * 4] = make_float4(ss0, ss1, ss2, ss3);
    __syncthreads();
    float tot = s_part[tid] + s_part[256 + tid] + s_part[512 + tid] + s_part[768 + tid];
    float invv = 1.f / fmaxf(sqrtf(tot), 1e-12f);
    __syncthreads();
    s_part[tid] = invv;
    __syncthreads();
    float* s_inv = s_part;

    float iv0[4], iv1[4];
#pragma unroll
    for (int nt = 0; nt < 4; ++nt) {
        int c0 = pw + nt * 8 + (lane & 3) * 2;
        iv0[nt] = s_inv[c0];
        iv1[nt] = s_inv[c0 + 1];
    }
    float bb0[4], bb1[4];
#pragma unroll
    for (int mt = 0; mt < 4; ++mt) {
        bb0[mt] = s_b[mt * 16 + (lane >> 2)];
        bb1[mt] = s_b[mt * 16 + (lane >> 2) + 8];
    }
    float l[4][4][4];
#pragma unroll
    for (int mt = 0; mt < 4; ++mt)
#pragma unroll
        for (int nt = 0; nt < 4; ++nt) {
            l[mt][nt][0] = acc[mt][nt][0] * iv0[nt] + bb0[mt];
            l[mt][nt][1] = acc[mt][nt][1] * iv1[nt] + bb0[mt];
            l[mt][nt][2] = acc[mt][nt][2] * iv0[nt] + bb1[mt];
            l[mt][nt][3] = acc[mt][nt][3] * iv1[nt] + bb1[mt];
        }
    float mx0[4], mx1[4];
#pragma unroll
    for (int nt = 0; nt < 4; ++nt) {
        float m0 = -1e30f, m1 = -1e30f;
#pragma unroll
        for (int mt = 0; mt < 4; ++mt) {
            m0 = fmaxf(m0, fmaxf(l[mt][nt][0], l[mt][nt][2]));
            m1 = fmaxf(m1, fmaxf(l[mt][nt][1], l[mt][nt][3]));
        }
#pragma unroll
        for (int s = 4; s < 32; s <<= 1) {
            m0 = fmaxf(m0, __shfl_xor_sync(0xffffffffu, m0, s));
            m1 = fmaxf(m1, __shfl_xor_sync(0xffffffffu, m1, s));
        }
        mx0[nt] = m0; mx1[nt] = m1;
    }
    float sm0[4], sm1[4];
#pragma unroll
    for (int nt = 0; nt < 4; ++nt) {
        float s0 = 0.f, s1 = 0.f;
#pragma unroll
        for (int mt = 0; mt < 4; ++mt) {
            l[mt][nt][0] = __expf(l[mt][nt][0] - mx0[nt]); s0 += l[mt][nt][0];
            l[mt][nt][2] = __expf(l[mt][nt][2] - mx0[nt]); s0 += l[mt][nt][2];
            l[mt][nt][1] = __expf(l[mt][nt][1] - mx1[nt]); s1 += l[mt][nt][1];
            l[mt][nt][3] = __expf(l[mt][nt][3] - mx1[nt]); s1 += l[mt][nt][3];
        }
#pragma unroll
        for (int s = 4; s < 32; s <<= 1) {
            s0 += __shfl_xor_sync(0xffffffffu, s0, s);
            s1 += __shfl_xor_sync(0xffffffffu, s1, s);
        }
        sm0[nt] = 1.f / s0; sm1[nt] = 1.f / s1;
    }
    float srow0[4] = {0, 0, 0, 0}, srow1[4] = {0, 0, 0, 0};
#pragma unroll
    for (int mt = 0; mt < 4; ++mt) {
        int r0 = mt * 16 + (lane >> 2);
#pragma unroll
        for (int nt = 0; nt < 4; ++nt) {
            int c0 = pw + nt * 8 + (lane & 3) * 2;
            float a0 = l[mt][nt][0] * sm0[nt];
            float a1 = l[mt][nt][1] * sm1[nt];
            float a2 = l[mt][nt][2] * sm0[nt];
            float a3 = l[mt][nt][3] * sm1[nt];
            srow0[mt] += a0 + a1;
            srow1[mt] += a2 + a3;
            *(uint32_t*)&aout[r0 * 264 + c0] = cvt2bf(a0 * iv0[nt], a1 * iv1[nt]);
            *(uint32_t*)&aout[(r0 + 8) * 264 + c0] = cvt2bf(a2 * iv0[nt], a3 * iv1[nt]);
        }
    }
#pragma unroll
    for (int mt = 0; mt < 4; ++mt) {
        float t0 = srow0[mt], t1 = srow1[mt];
        t0 += __shfl_xor_sync(0xffffffffu, t0, 1); t0 += __shfl_xor_sync(0xffffffffu, t0, 2);
        t1 += __shfl_xor_sync(0xffffffffu, t1, 1); t1 += __shfl_xor_sync(0xffffffffu, t1, 2);
        if ((lane & 3) == 0) {
            atomicAdd(&s_asum[mt * 16 + (lane >> 2)], t0);
            atomicAdd(&s_asum[mt * 16 + (lane >> 2) + 8], t1);
        }
    }
    __syncthreads();
    __nv_bfloat16* ga = g_a + (size_t)(n * Kdim) * Pdim + p0;
#pragma unroll
    for (int r = 0; r < 8; ++r) {
        int f = tid + r * 256;
        int row = f >> 5, seg = f & 31;
        *(uint4*)(ga + (size_t)row * Pdim + seg * 8) = *(uint4*)&aout[row * 264 + seg * 8];
    }
    if (tid < 64) g_asum_p[(n * 16 + blockIdx.x) * Kdim + tid] = s_asum[tid];
}

// =====================================================================
// K_vlad_mma: single-term bf16 x (raw), bf16 a'. Register-prefetch pipeline.
// =====================================================================
__global__ __launch_bounds__(256, 2) void k_vlad_mma(const float* __restrict__ x) {
    __shared__ __align__(16) __nv_bfloat16 xh[128 * 72];
    __shared__ __align__(16) __nv_bfloat16 as_[64 * 72];

    const int n = blockIdx.y, ps = blockIdx.x;
    const int tid = threadIdx.x;
    const int w = tid >> 5, lane = tid & 31;
    const int pb0 = ps * (Pdim / PSPLIT);

    const uint32_t u_xh = smem_u32(xh), u_as = smem_u32(as_);

    float acc[8][4];
#pragma unroll
    for (int a = 0; a < 8; ++a)
#pragma unroll
        for (int b = 0; b < 4; ++b) acc[a][b] = 0.f;

    const float* xg = x + (size_t)n * Cdim * Pdim;
    const __nv_bfloat16* ga = g_a + (size_t)(n * Kdim) * Pdim;

    const int xrow = tid >> 4, xcol4 = tid & 15;
    const int arow = tid >> 3, aseg = tid & 7;

    float4 vx[8];
    uint4 va[2];
#pragma unroll
    for (int r = 0; r < 8; ++r)
        vx[r] = *(const float4*)(xg + (size_t)(xrow + r * 16) * Pdim + pb0 + xcol4 * 4);
#pragma unroll
    for (int r = 0; r < 2; ++r)
        va[r] = *(const uint4*)(ga + (size_t)(arow + r * 32) * Pdim + pb0 + aseg * 8);

    for (int pc = 0; pc < 16; ++pc) {
#pragma unroll
        for (int r = 0; r < 8; ++r) {
            uint32_t h01 = cvt2bf(vx[r].x, vx[r].y);
            uint32_t h23 = cvt2bf(vx[r].z, vx[r].w);
            *(uint2*)&xh[(xrow + r * 16) * 72 + xcol4 * 4] = make_uint2(h01, h23);
        }
#pragma unroll
        for (int r = 0; r < 2; ++r)
            *(uint4*)&as_[(arow + r * 32) * 72 + aseg * 8] = va[r];
        __syncthreads();

        if (pc < 15) {
            const int pb = pb0 + (pc + 1) * 64;
#pragma unroll
            for (int r = 0; r < 8; ++r)
                vx[r] = *(const float4*)(xg + (size_t)(xrow + r * 16) * Pdim + pb + xcol4 * 4);
#pragma unroll
            for (int r = 0; r < 2; ++r)
                va[r] = *(const uint4*)(ga + (size_t)(arow + r * 32) * Pdim + pb + aseg * 8);
        }

#pragma unroll
        for (int ks = 0; ks < 4; ++ks) {
            uint32_t ah[4];
            uint32_t offA = (uint32_t)(((w * 16 + (lane & 15)) * 72 + ks * 16 + (lane >> 4) * 8) * 2);
            ldsm_x4(ah, u_xh + offA);
#pragma unroll
            for (int ntp = 0; ntp < 4; ++ntp) {
                uint32_t b4[4];
                int row = ntp * 16 + ((lane >> 4) << 3) + (lane & 7);
                int col = ks * 16 + ((lane >> 3) & 1) * 8;
                ldsm_x4(b4, u_as + (uint32_t)((row * 72 + col) * 2));
                mma_bf16(acc[2 * ntp], ah, b4);
                mma_bf16(acc[2 * ntp + 1], ah, b4 + 2);
            }
        }
        __syncthreads();
    }
    float* vp = g_vpart + (size_t)(n * PSPLIT + ps) * (Cdim * Kdim);
    int r0 = w * 16 + (lane >> 2);
    int c0 = (lane & 3) * 2;
#pragma unroll
    for (int nt = 0; nt < 8; ++nt) {
        float2 t0 = make_float2(acc[nt][0], acc[nt][1]);
        float2 t1 = make_float2(acc[nt][2], acc[nt][3]);
        *(float2*)&vp[(size_t)r0 * Kdim + nt * 8 + c0] = t0;
        *(float2*)&vp[(size_t)(r0 + 8) * Kdim + nt * 8 + c0] = t1;
    }
}

// =====================================================================
// K_final: 1024 threads.
// =====================================================================
__global__ __launch_bounds__(1024) void k_final(const float* __restrict__ cent,
                                                float* __restrict__ out) {
    const int n = blockIdx.x;
    const int tid = threadIdx.x;
    __shared__ float vl[Kdim * 129];
    __shared__ float rn[Kdim];
    __shared__ float redb[32];
    __shared__ float s_asum[64];
    __shared__ float gscale;

    if (tid < 64) {
        float s = 0.f;
#pragma unroll
        for (int t = 0; t < 16; ++t) s += g_asum_p[(n * 16 + t) * Kdim + tid];
        s_asum[tid] = s;
    }
    __syncthreads();

    const float* vp = g_vpart + (size_t)(n * PSPLIT) * (Cdim * Kdim);
#pragma unroll
    for (int it = 0; it < 2; ++it) {
        int i4 = tid + it * 1024;
        int idx = i4 * 4;
        float4 s = *(const float4*)(vp + idx);
        float4 s1 = *(const float4*)(vp + (Cdim * Kdim) + idx);
        float4 s2 = *(const float4*)(vp + 2 * (Cdim * Kdim) + idx);
        float4 s3 = *(const float4*)(vp + 3 * (Cdim * Kdim) + idx);
        s.x += s1.x + s2.x + s3.x;
        s.y += s1.y + s2.y + s3.y;
        s.z += s1.z + s2.z + s3.z;
        s.w += s1.w + s2.w + s3.w;
        int c = idx >> 6, k = idx & 63;
        vl[(k + 0) * 129 + c] = s.x - s_asum[k + 0] * cent[(k + 0) * Cdim + c];
        vl[(k + 1) * 129 + c] = s.y - s_asum[k + 1] * cent[(k + 1) * Cdim + c];
        vl[(k + 2) * 129 + c] = s.z - s_asum[k + 2] * cent[(k + 2) * Cdim + c];
        vl[(k + 3) * 129 + c] = s.w - s_asum[k + 3] * cent[(k + 3) * Cdim + c];
    }
    __syncthreads();

    int w = tid >> 5, lane = tid & 31;
#pragma unroll
    for (int kk = 0; kk < 2; ++kk) {
        int k = w * 2 + kk;
        float t = 0.f;
#pragma unroll
        for (int m = 0; m < 4; ++m) {
            float v = vl[k * 129 + lane + m * 32];
            t += v * v;
        }
#pragma unroll
        for (int off = 16; off > 0; off >>= 1) t += __shfl_xor_sync(0xffffffffu, t, off);
        if (lane == 0) rn[k] = 1.f / fmaxf(sqrtf(t), 1e-12f);
    }
    __syncthreads();

    float tot = 0.f;
#pragma unroll
    for (int it = 0; it < 8; ++it) {
        int idx = tid + it * 1024;
        int k = idx >> 7, c = idx & 127;
        float v = vl[k * 129 + c] * rn[k];
        vl[k * 129 + c] = v;
        tot += v * v;
    }
#pragma unroll
    for (int off = 16; off > 0; off >>= 1) tot += __shfl_xor_sync(0xffffffffu, tot, off);
    if (lane == 0) redb[w] = tot;
    __syncthreads();
    if (tid == 0) {
        float t = 0.f;
#pragma unroll
        for (int q = 0; q < 32; ++q) t += redb[q];
        gscale = 1.f / fmaxf(sqrtf(t), 1e-12f);
    }
    __syncthreads();
    float gs = gscale;
#pragma unroll
    for (int it = 0; it < 8; ++it) {
        int idx = tid + it * 1024;
        int k = idx >> 7, c = idx & 127;
        out[(size_t)n * (Kdim * Cdim) + idx] = vl[k * 129 + c] * gs;
    }
}

// =====================================================================
extern "C" void kernel_launch(void* const* d_in, const int* in_sizes, int n_in,
                              void* d_out, int out_size) {
    const float* x      = (const float*)d_in[0];
    const float* cent   = (const float*)d_in[2];
    const float* conv_w = (const float*)d_in[3];
    const float* conv_b = (const float*)d_in[4];
    float* out = (float*)d_out;

    cudaFuncSetAttribute(k_logits_mma, cudaFuncAttributeMaxDynamicSharedMemorySize, L_SMEM);

    k_logits_mma<<<dim3(16, 64), 256, L_SMEM>>>(x, conv_w, conv_b);
    k_vlad_mma<<<dim3(PSPLIT, 64), 256>>>(x);
    k_final<<<64, 1024>>>(cent, out);
}

// round 8
// speedup vs baseline: 1.0763x; 1.0307x over previous
#include <cuda_runtime.h>
#include <cuda_bf16.h>
#include <cstdint>
#include <math.h>

#define Nn 64
#define Cdim 128
#define Pdim 4096
#define Kdim 64
#define PSPLIT 4

// ---- device scratch ----
__device__ __nv_bfloat16 g_a[(size_t)Nn * Kdim * Pdim];      // 32 MB  (a * inv_norm, bf16)
__device__ float g_asum_p[Nn * 32 * Kdim];                    // 512 KB (per-tile asum partials)
__device__ float g_vpart[(size_t)Nn * PSPLIT * Cdim * Kdim];  // 8 MB   [n][ps][c][k]

// ---- mma / ldmatrix wrappers ----
__device__ __forceinline__ uint32_t smem_u32(const void* p) {
    uint32_t a;
    asm("{ .reg .u64 t; cvta.to.shared.u64 t, %1; cvt.u32.u64 %0, t; }" : "=r"(a) : "l"(p));
    return a;
}
__device__ __forceinline__ void ldsm_x4(uint32_t* r, uint32_t addr) {
    asm volatile("ldmatrix.sync.aligned.m8n8.x4.shared.b16 {%0,%1,%2,%3}, [%4];"
                 : "=r"(r[0]), "=r"(r[1]), "=r"(r[2]), "=r"(r[3]) : "r"(addr));
}
__device__ __forceinline__ void ldsm_x2_trans(uint32_t* r, uint32_t addr) {
    asm volatile("ldmatrix.sync.aligned.m8n8.x2.trans.shared.b16 {%0,%1}, [%2];"
                 : "=r"(r[0]), "=r"(r[1]) : "r"(addr));
}
__device__ __forceinline__ void mma_bf16(float* d, const uint32_t* a, const uint32_t* b) {
    asm volatile(
        "mma.sync.aligned.m16n8k16.row.col.f32.bf16.bf16.f32 "
        "{%0,%1,%2,%3}, {%4,%5,%6,%7}, {%8,%9}, {%0,%1,%2,%3};"
        : "+f"(d[0]), "+f"(d[1]), "+f"(d[2]), "+f"(d[3])
        : "r"(a[0]), "r"(a[1]), "r"(a[2]), "r"(a[3]), "r"(b[0]), "r"(b[1]));
}
__device__ __forceinline__ void split_bf16(float v, __nv_bfloat16& h, __nv_bfloat16& l) {
    h = __float2bfloat16(v);
    l = __float2bfloat16(v - __bfloat162float(h));
}
__device__ __forceinline__ uint32_t cvt2bf(float lo, float hi) {
    uint32_t r;
    asm("cvt.rn.bf16x2.f32 %0, %1, %2;" : "=r"(r) : "f"(hi), "f"(lo));
    return r;
}
__device__ __forceinline__ float bfp_lo(uint32_t pair) { return __uint_as_float(pair << 16); }
__device__ __forceinline__ float bfp_hi(uint32_t pair) { return __uint_as_float(pair & 0xFFFF0000u); }

// =====================================================================
// K_logits_mma: per (n, 128-pixel tile). 3 CTAs/SM target.
// =====================================================================
#define XPLANE 4352                 // 32*136 elems per x plane
#define OFF_WH 0                    // W hi: 64*136*2 = 17408 B
#define OFF_WL 17408
#define OFF_XB 34816                // 4 x planes * 8704 B = 34816
#define OFF_SP 69632                // s_part 8*128 floats = 4096 B
#define OFF_SA 73728                // s_asum 64 floats
#define OFF_SB 73984                // s_b 64 floats
#define L_SMEM 74240

__global__ __launch_bounds__(256, 3) void k_logits_mma(const float* __restrict__ x,
                                                       const float* __restrict__ conv_w,
                                                       const float* __restrict__ conv_b) {
    extern __shared__ __align__(16) char dsm[];
    __nv_bfloat16* wh = (__nv_bfloat16*)(dsm + OFF_WH);
    __nv_bfloat16* wl = (__nv_bfloat16*)(dsm + OFF_WL);
    __nv_bfloat16* xb = (__nv_bfloat16*)(dsm + OFF_XB);
    __nv_bfloat16* aout = xb;                    // alias (buffer 0 region, 17408 B)
    float* s_part = (float*)(dsm + OFF_SP);
    float* s_asum = (float*)(dsm + OFF_SA);
    float* s_b = (float*)(dsm + OFF_SB);

    const int n = blockIdx.y;
    const int p0 = blockIdx.x * 128;
    const int tid = threadIdx.x;
    const int w = tid >> 5, lane = tid & 31;
    const int pw = w * 16;                       // warp's 16-pixel slice

    const uint32_t u_wh = smem_u32(wh), u_wl = smem_u32(wl);

    // stage W hi/lo (64x128, pitch 136)
#pragma unroll
    for (int r = 0; r < 8; ++r) {
        int f4 = tid + r * 256;
        int row = f4 >> 5, col4 = f4 & 31;
        float4 v = *(const float4*)(conv_w + row * 128 + col4 * 4);
        __nv_bfloat16 h, l;
        split_bf16(v.x, h, l); wh[row * 136 + col4 * 4 + 0] = h; wl[row * 136 + col4 * 4 + 0] = l;
        split_bf16(v.y, h, l); wh[row * 136 + col4 * 4 + 1] = h; wl[row * 136 + col4 * 4 + 1] = l;
        split_bf16(v.z, h, l); wh[row * 136 + col4 * 4 + 2] = h; wl[row * 136 + col4 * 4 + 2] = l;
        split_bf16(v.w, h, l); wh[row * 136 + col4 * 4 + 3] = h; wl[row * 136 + col4 * 4 + 3] = l;
    }
    if (tid < 64) { s_b[tid] = conv_b[tid]; s_asum[tid] = 0.f; }

    float acc[4][2][4];
#pragma unroll
    for (int a = 0; a < 4; ++a)
#pragma unroll
        for (int b = 0; b < 2; ++b)
#pragma unroll
            for (int c = 0; c < 4; ++c) acc[a][b][c] = 0.f;

    const float* xg = x + (size_t)n * Cdim * Pdim + p0;
    const int rbase = tid >> 5;          // 0..7
    const int col4 = tid & 31;           // pixel quad (0..31)

    float ss0 = 0.f, ss1 = 0.f, ss2 = 0.f, ss3 = 0.f;
    float4 vx[4];

    // prologue: chunk 0 load + stage into buffer 0
#pragma unroll
    for (int r = 0; r < 4; ++r)
        vx[r] = *(const float4*)(xg + (size_t)(rbase + 8 * r) * Pdim + col4 * 4);
    {
        __nv_bfloat16* cxh = xb;
        __nv_bfloat16* cxl = xb + XPLANE;
#pragma unroll
        for (int r = 0; r < 4; ++r) {
            float4 v = vx[r];
            ss0 += v.x * v.x; ss1 += v.y * v.y; ss2 += v.z * v.z; ss3 += v.w * v.w;
            uint32_t h01 = cvt2bf(v.x, v.y), h23 = cvt2bf(v.z, v.w);
            float l0 = v.x - bfp_lo(h01), l1 = v.y - bfp_hi(h01);
            float l2 = v.z - bfp_lo(h23), l3 = v.w - bfp_hi(h23);
            int row = rbase + 8 * r;
            *(uint2*)&cxh[row * 136 + col4 * 4] = make_uint2(h01, h23);
            *(uint2*)&cxl[row * 136 + col4 * 4] = make_uint2(cvt2bf(l0, l1), cvt2bf(l2, l3));
        }
    }
    __syncthreads();

#pragma unroll
    for (int cbi = 0; cbi < 4; ++cbi) {
        const int cb = cbi * 32;
        if (cbi < 3) {
#pragma unroll
            for (int r = 0; r < 4; ++r)
                vx[r] = *(const float4*)(xg + (size_t)(cb + 32 + rbase + 8 * r) * Pdim + col4 * 4);
        }

        const uint32_t u_xh = smem_u32(xb + (cbi & 1) * 2 * XPLANE);
        const uint32_t u_xl = u_xh + XPLANE * 2;
#pragma unroll
        for (int ks = 0; ks < 2; ++ks) {
            uint32_t bh[2][2], bl[2][2];
#pragma unroll
            for (int nt = 0; nt < 2; ++nt) {
                uint32_t off = (uint32_t)(((ks * 16 + (lane & 15)) * 136 + pw + nt * 8) * 2);
                ldsm_x2_trans(bh[nt], u_xh + off);
                ldsm_x2_trans(bl[nt], u_xl + off);
            }
#pragma unroll
            for (int mt = 0; mt < 4; ++mt) {
                uint32_t ah[4], al[4];
                uint32_t off = (uint32_t)(((mt * 16 + (lane & 15)) * 136 + cb + ks * 16 + (lane >> 4) * 8) * 2);
                ldsm_x4(ah, u_wh + off);
                ldsm_x4(al, u_wl + off);
#pragma unroll
                for (int nt = 0; nt < 2; ++nt) {
                    mma_bf16(acc[mt][nt], ah, bh[nt]);
                    mma_bf16(acc[mt][nt], ah, bl[nt]);
                    mma_bf16(acc[mt][nt], al, bh[nt]);
                }
            }
        }

        if (cbi < 3) {
            __nv_bfloat16* cxh = xb + ((cbi + 1) & 1) * 2 * XPLANE;
            __nv_bfloat16* cxl = cxh + XPLANE;
#pragma unroll
            for (int r = 0; r < 4; ++r) {
                float4 v = vx[r];
                ss0 += v.x * v.x; ss1 += v.y * v.y; ss2 += v.z * v.z; ss3 += v.w * v.w;
                uint32_t h01 = cvt2bf(v.x, v.y), h23 = cvt2bf(v.z, v.w);
                float l0 = v.x - bfp_lo(h01), l1 = v.y - bfp_hi(h01);
                float l2 = v.z - bfp_lo(h23), l3 = v.w - bfp_hi(h23);
                int row = rbase + 8 * r;
                *(uint2*)&cxh[row * 136 + col4 * 4] = make_uint2(h01, h23);
                *(uint2*)&cxl[row * 136 + col4 * 4] = make_uint2(cvt2bf(l0, l1), cvt2bf(l2, l3));
            }
        }
        __syncthreads();
    }

    // sumsq reduce: 8 partials per pixel. Read into reg, barrier, overwrite in place.
    *(float4*)&s_part[rbase * 128 + col4 * 4] = make_float4(ss0, ss1, ss2, ss3);
    __syncthreads();
    float tot = 0.f;
    if (tid < 128) {
#pragma unroll
        for (int q = 0; q < 8; ++q) tot += s_part[q * 128 + tid];
    }
    __syncthreads();
    if (tid < 128) s_part[tid] = 1.f / fmaxf(sqrtf(tot), 1e-12f);
    __syncthreads();
    float* s_inv = s_part;

    float iv0[2], iv1[2];
#pragma unroll
    for (int nt = 0; nt < 2; ++nt) {
        int c0 = pw + nt * 8 + (lane & 3) * 2;
        iv0[nt] = s_inv[c0];
        iv1[nt] = s_inv[c0 + 1];
    }
    float bb0[4], bb1[4];
#pragma unroll
    for (int mt = 0; mt < 4; ++mt) {
        bb0[mt] = s_b[mt * 16 + (lane >> 2)];
        bb1[mt] = s_b[mt * 16 + (lane >> 2) + 8];
    }
    float l[4][2][4];
#pragma unroll
    for (int mt = 0; mt < 4; ++mt)
#pragma unroll
        for (int nt = 0; nt < 2; ++nt) {
            l[mt][nt][0] = acc[mt][nt][0] * iv0[nt] + bb0[mt];
            l[mt][nt][1] = acc[mt][nt][1] * iv1[nt] + bb0[mt];
            l[mt][nt][2] = acc[mt][nt][2] * iv0[nt] + bb1[mt];
            l[mt][nt][3] = acc[mt][nt][3] * iv1[nt] + bb1[mt];
        }
    float mx0[2], mx1[2];
#pragma unroll
    for (int nt = 0; nt < 2; ++nt) {
        float m0 = -1e30f, m1 = -1e30f;
#pragma unroll
        for (int mt = 0; mt < 4; ++mt) {
            m0 = fmaxf(m0, fmaxf(l[mt][nt][0], l[mt][nt][2]));
            m1 = fmaxf(m1, fmaxf(l[mt][nt][1], l[mt][nt][3]));
        }
#pragma unroll
        for (int s = 4; s < 32; s <<= 1) {
            m0 = fmaxf(m0, __shfl_xor_sync(0xffffffffu, m0, s));
            m1 = fmaxf(m1, __shfl_xor_sync(0xffffffffu, m1, s));
        }
        mx0[nt] = m0; mx1[nt] = m1;
    }
    float sm0[2], sm1[2];
#pragma unroll
    for (int nt = 0; nt < 2; ++nt) {
        float s0 = 0.f, s1 = 0.f;
#pragma unroll
        for (int mt = 0; mt < 4; ++mt) {
            l[mt][nt][0] = __expf(l[mt][nt][0] - mx0[nt]); s0 += l[mt][nt][0];
            l[mt][nt][2] = __expf(l[mt][nt][2] - mx0[nt]); s0 += l[mt][nt][2];
            l[mt][nt][1] = __expf(l[mt][nt][1] - mx1[nt]); s1 += l[mt][nt][1];
            l[mt][nt][3] = __expf(l[mt][nt][3] - mx1[nt]); s1 += l[mt][nt][3];
        }
#pragma unroll
        for (int s = 4; s < 32; s <<= 1) {
            s0 += __shfl_xor_sync(0xffffffffu, s0, s);
            s1 += __shfl_xor_sync(0xffffffffu, s1, s);
        }
        sm0[nt] = 1.f / s0; sm1[nt] = 1.f / s1;
    }
    float srow0[4] = {0, 0, 0, 0}, srow1[4] = {0, 0, 0, 0};
#pragma unroll
    for (int mt = 0; mt < 4; ++mt) {
        int r0 = mt * 16 + (lane >> 2);
#pragma unroll
        for (int nt = 0; nt < 2; ++nt) {
            int c0 = pw + nt * 8 + (lane & 3) * 2;
            float a0 = l[mt][nt][0] * sm0[nt];
            float a1 = l[mt][nt][1] * sm1[nt];
            float a2 = l[mt][nt][2] * sm0[nt];
            float a3 = l[mt][nt][3] * sm1[nt];
            srow0[mt] += a0 + a1;
            srow1[mt] += a2 + a3;
            *(uint32_t*)&aout[r0 * 136 + c0] = cvt2bf(a0 * iv0[nt], a1 * iv1[nt]);
            *(uint32_t*)&aout[(r0 + 8) * 136 + c0] = cvt2bf(a2 * iv0[nt], a3 * iv1[nt]);
        }
    }
#pragma unroll
    for (int mt = 0; mt < 4; ++mt) {
        float t0 = srow0[mt], t1 = srow1[mt];
        t0 += __shfl_xor_sync(0xffffffffu, t0, 1); t0 += __shfl_xor_sync(0xffffffffu, t0, 2);
        t1 += __shfl_xor_sync(0xffffffffu, t1, 1); t1 += __shfl_xor_sync(0xffffffffu, t1, 2);
        if ((lane & 3) == 0) {
            atomicAdd(&s_asum[mt * 16 + (lane >> 2)], t0);
            atomicAdd(&s_asum[mt * 16 + (lane >> 2) + 8], t1);
        }
    }
    __syncthreads();
    __nv_bfloat16* ga = g_a + (size_t)(n * Kdim) * Pdim + p0;
#pragma unroll
    for (int r = 0; r < 4; ++r) {
        int f = tid + r * 256;
        int row = f >> 4, seg = f & 15;
        *(uint4*)(ga + (size_t)row * Pdim + seg * 8) = *(uint4*)&aout[row * 136 + seg * 8];
    }
    if (tid < 64) g_asum_p[(n * 32 + blockIdx.x) * Kdim + tid] = s_asum[tid];
}

// =====================================================================
// K_vlad_mma: single-term bf16 x (raw), bf16 a'. Register-prefetch pipeline.
// =====================================================================
__global__ __launch_bounds__(256, 2) void k_vlad_mma(const float* __restrict__ x) {
    __shared__ __align__(16) __nv_bfloat16 xh[128 * 72];
    __shared__ __align__(16) __nv_bfloat16 as_[64 * 72];

    const int n = blockIdx.y, ps = blockIdx.x;
    const int tid = threadIdx.x;
    const int w = tid >> 5, lane = tid & 31;
    const int pb0 = ps * (Pdim / PSPLIT);

    const uint32_t u_xh = smem_u32(xh), u_as = smem_u32(as_);

    float acc[8][4];
#pragma unroll
    for (int a = 0; a < 8; ++a)
#pragma unroll
        for (int b = 0; b < 4; ++b) acc[a][b] = 0.f;

    const float* xg = x + (size_t)n * Cdim * Pdim;
    const __nv_bfloat16* ga = g_a + (size_t)(n * Kdim) * Pdim;

    const int xrow = tid >> 4, xcol4 = tid & 15;
    const int arow = tid >> 3, aseg = tid & 7;

    float4 vx[8];
    uint4 va[2];
#pragma unroll
    for (int r = 0; r < 8; ++r)
        vx[r] = *(const float4*)(xg + (size_t)(xrow + r * 16) * Pdim + pb0 + xcol4 * 4);
#pragma unroll
    for (int r = 0; r < 2; ++r)
        va[r] = *(const uint4*)(ga + (size_t)(arow + r * 32) * Pdim + pb0 + aseg * 8);

    for (int pc = 0; pc < 16; ++pc) {
#pragma unroll
        for (int r = 0; r < 8; ++r) {
            uint32_t h01 = cvt2bf(vx[r].x, vx[r].y);
            uint32_t h23 = cvt2bf(vx[r].z, vx[r].w);
            *(uint2*)&xh[(xrow + r * 16) * 72 + xcol4 * 4] = make_uint2(h01, h23);
        }
#pragma unroll
        for (int r = 0; r < 2; ++r)
            *(uint4*)&as_[(arow + r * 32) * 72 + aseg * 8] = va[r];
        __syncthreads();

        if (pc < 15) {
            const int pb = pb0 + (pc + 1) * 64;
#pragma unroll
            for (int r = 0; r < 8; ++r)
                vx[r] = *(const float4*)(xg + (size_t)(xrow + r * 16) * Pdim + pb + xcol4 * 4);
#pragma unroll
            for (int r = 0; r < 2; ++r)
                va[r] = *(const uint4*)(ga + (size_t)(arow + r * 32) * Pdim + pb + aseg * 8);
        }

#pragma unroll
        for (int ks = 0; ks < 4; ++ks) {
            uint32_t ah[4];
            uint32_t offA = (uint32_t)(((w * 16 + (lane & 15)) * 72 + ks * 16 + (lane >> 4) * 8) * 2);
            ldsm_x4(ah, u_xh + offA);
#pragma unroll
            for (int ntp = 0; ntp < 4; ++ntp) {
                uint32_t b4[4];
                int row = ntp * 16 + ((lane >> 4) << 3) + (lane & 7);
                int col = ks * 16 + ((lane >> 3) & 1) * 8;
                ldsm_x4(b4, u_as + (uint32_t)((row * 72 + col) * 2));
                mma_bf16(acc[2 * ntp], ah, b4);
                mma_bf16(acc[2 * ntp + 1], ah, b4 + 2);
            }
        }
        __syncthreads();
    }
    float* vp = g_vpart + (size_t)(n * PSPLIT + ps) * (Cdim * Kdim);
    int r0 = w * 16 + (lane >> 2);
    int c0 = (lane & 3) * 2;
#pragma unroll
    for (int nt = 0; nt < 8; ++nt) {
        float2 t0 = make_float2(acc[nt][0], acc[nt][1]);
        float2 t1 = make_float2(acc[nt][2], acc[nt][3]);
        *(float2*)&vp[(size_t)r0 * Kdim + nt * 8 + c0] = t0;
        *(float2*)&vp[(size_t)(r0 + 8) * Kdim + nt * 8 + c0] = t1;
    }
}

// =====================================================================
// K_final: 1024 threads.
// =====================================================================
__global__ __launch_bounds__(1024) void k_final(const float* __restrict__ cent,
                                                float* __restrict__ out) {
    const int n = blockIdx.x;
    const int tid = threadIdx.x;
    __shared__ float vl[Kdim * 129];
    __shared__ float rn[Kdim];
    __shared__ float redb[32];
    __shared__ float s_asum[64];
    __shared__ float gscale;

    if (tid < 64) {
        float s = 0.f;
#pragma unroll
        for (int t = 0; t < 32; ++t) s += g_asum_p[(n * 32 + t) * Kdim + tid];
        s_asum[tid] = s;
    }
    __syncthreads();

    const float* vp = g_vpart + (size_t)(n * PSPLIT) * (Cdim * Kdim);
#pragma unroll
    for (int it = 0; it < 2; ++it) {
        int i4 = tid + it * 1024;
        int idx = i4 * 4;
        float4 s = *(const float4*)(vp + idx);
        float4 s1 = *(const float4*)(vp + (Cdim * Kdim) + idx);
        float4 s2 = *(const float4*)(vp + 2 * (Cdim * Kdim) + idx);
        float4 s3 = *(const float4*)(vp + 3 * (Cdim * Kdim) + idx);
        s.x += s1.x + s2.x + s3.x;
        s.y += s1.y + s2.y + s3.y;
        s.z += s1.z + s2.z + s3.z;
        s.w += s1.w + s2.w + s3.w;
        int c = idx >> 6, k = idx & 63;
        vl[(k + 0) * 129 + c] = s.x - s_asum[k + 0] * cent[(k + 0) * Cdim + c];
        vl[(k + 1) * 129 + c] = s.y - s_asum[k + 1] * cent[(k + 1) * Cdim + c];
        vl[(k + 2) * 129 + c] = s.z - s_asum[k + 2] * cent[(k + 2) * Cdim + c];
        vl[(k + 3) * 129 + c] = s.w - s_asum[k + 3] * cent[(k + 3) * Cdim + c];
    }
    __syncthreads();

    int w = tid >> 5, lane = tid & 31;
#pragma unroll
    for (int kk = 0; kk < 2; ++kk) {
        int k = w * 2 + kk;
        float t = 0.f;
#pragma unroll
        for (int m = 0; m < 4; ++m) {
            float v = vl[k * 129 + lane + m * 32];
            t += v * v;
        }
#pragma unroll
        for (int off = 16; off > 0; off >>= 1) t += __shfl_xor_sync(0xffffffffu, t, off);
        if (lane == 0) rn[k] = 1.f / fmaxf(sqrtf(t), 1e-12f);
    }
    __syncthreads();

    float tot = 0.f;
#pragma unroll
    for (int it = 0; it < 8; ++it) {
        int idx = tid + it * 1024;
        int k = idx >> 7, c = idx & 127;
        float v = vl[k * 129 + c] * rn[k];
        vl[k * 129 + c] = v;
        tot += v * v;
    }
#pragma unroll
    for (int off = 16; off > 0; off >>= 1) tot += __shfl_xor_sync(0xffffffffu, tot, off);
    if (lane == 0) redb[w] = tot;
    __syncthreads();
    if (tid == 0) {
        float t = 0.f;
#pragma unroll
        for (int q = 0; q < 32; ++q) t += redb[q];
        gscale = 1.f / fmaxf(sqrtf(t), 1e-12f);
    }
    __syncthreads();
    float gs = gscale;
#pragma unroll
    for (int it = 0; it < 8; ++it) {
        int idx = tid + it * 1024;
        int k = idx >> 7, c = idx & 127;
        out[(size_t)n * (Kdim * Cdim) + idx] = vl[k * 129 + c] * gs;
    }
}

// =====================================================================
extern "C" void kernel_launch(void* const* d_in, const int* in_sizes, int n_in,
                              void* d_out, int out_size) {
    const float* x      = (const float*)d_in[0];
    const float* cent   = (const float*)d_in[2];
    const float* conv_w = (const float*)d_in[3];
    const float* conv_b = (const float*)d_in[4];
    float* out = (float*)d_out;

    cudaFuncSetAttribute(k_logits_mma, cudaFuncAttributeMaxDynamicSharedMemorySize, L_SMEM);

    k_logits_mma<<<dim3(32, 64), 256, L_SMEM>>>(x, conv_w, conv_b);
    k_vlad_mma<<<dim3(PSPLIT, 64), 256>>>(x);
    k_final<<<64, 1024>>>(cent, out);
}